// round 2
// baseline (speedup 1.0000x reference)
#include <cuda_runtime.h>
#include <cstdint>

// Problem constants
constexpr int Tt = 1024;   // timesteps
constexpr int Bb = 128;    // batch
constexpr int Ii = 256;    // input dim
constexpr int Hh = 512;    // hidden dim
constexpr long long TBH = (long long)Tt * Bb * Hh;   // output region size

// -------------------------------------------------------------------------
// packed fp32 helpers (Blackwell f32x2 pipe; exact fp32 semantics)
// -------------------------------------------------------------------------
__device__ __forceinline__ void ffma2(unsigned long long& d,
                                      unsigned long long a,
                                      unsigned long long b) {
    asm("fma.rn.f32x2 %0, %1, %2, %0;" : "+l"(d) : "l"(a), "l"(b));
}
__device__ __forceinline__ unsigned long long dup2(float x) {
    unsigned long long r;
    asm("mov.b64 %0, {%1, %1};" : "=l"(r) : "f"(x));
    return r;
}
__device__ __forceinline__ float2 unpk(unsigned long long v) {
    float2 r;
    asm("mov.b64 {%0, %1}, %2;" : "=f"(r.x), "=f"(r.y) : "l"(v));
    return r;
}

// accurate tanh that survives --use_fast_math
__device__ __forceinline__ float tanh_acc(float x) {
    float ax = fabsf(x);
    float e  = __expf(-2.0f * ax);
    float r  = (1.0f - e) / (1.0f + e);
    return copysignf(r, x);
}

// =========================================================================
// Kernel 1: xw = x @ Wi^T  into d_out[0 : T*B*H)
//   CTA tile 128x128, K-chunks of 32, 256 threads.
//   Thread n-tile: two contiguous 4-col groups {4nt..+3} and {64+4nt..+3}
//   (16B chunks tile banks exactly -> conflict-free; f32x2 pairs natural).
// =========================================================================
__global__ void __launch_bounds__(256, 2)
xw_gemm_kernel(const float* __restrict__ x,
               const float* __restrict__ Wi,
               float* __restrict__ out)
{
    __shared__ float As[32][132];   // [k][m], padded
    __shared__ float Bs[32][132];   // [k][n], padded

    const int m0 = (blockIdx.x >> 2) * 128;
    const int n0 = (blockIdx.x & 3) * 128;
    const int tid = threadIdx.x;
    const int mt = tid >> 4;                  // 0..15 -> m rows mt*8..+7
    const int nt = tid & 15;                  // 0..15 -> n cols 4nt..+3, 64+4nt..+3

    unsigned long long acc2[8][4];
    #pragma unroll
    for (int i = 0; i < 8; i++)
        #pragma unroll
        for (int j = 0; j < 4; j++) acc2[i][j] = 0ULL;

    for (int k0 = 0; k0 < Ii; k0 += 32) {
        #pragma unroll
        for (int r = 0; r < 4; r++) {
            int f   = tid + r * 256;
            int row = f >> 3;
            int kq  = (f & 7) << 2;
            float4 va = *reinterpret_cast<const float4*>(
                &x[(size_t)(m0 + row) * Ii + k0 + kq]);
            As[kq + 0][row] = va.x; As[kq + 1][row] = va.y;
            As[kq + 2][row] = va.z; As[kq + 3][row] = va.w;
            float4 vb = *reinterpret_cast<const float4*>(
                &Wi[(size_t)(n0 + row) * Ii + k0 + kq]);
            Bs[kq + 0][row] = vb.x; Bs[kq + 1][row] = vb.y;
            Bs[kq + 2][row] = vb.z; Bs[kq + 3][row] = vb.w;
        }
        __syncthreads();

        #pragma unroll 4
        for (int kk = 0; kk < 32; kk++) {
            float4 av0 = *reinterpret_cast<const float4*>(&As[kk][mt * 8]);
            float4 av1 = *reinterpret_cast<const float4*>(&As[kk][mt * 8 + 4]);
            ulonglong2 b0 = *reinterpret_cast<const ulonglong2*>(&Bs[kk][nt * 4]);
            ulonglong2 b1 = *reinterpret_cast<const ulonglong2*>(&Bs[kk][64 + nt * 4]);
            float am[8] = {av0.x, av0.y, av0.z, av0.w, av1.x, av1.y, av1.z, av1.w};
            #pragma unroll
            for (int i = 0; i < 8; i++) {
                unsigned long long d = dup2(am[i]);
                ffma2(acc2[i][0], d, b0.x);
                ffma2(acc2[i][1], d, b0.y);
                ffma2(acc2[i][2], d, b1.x);
                ffma2(acc2[i][3], d, b1.y);
            }
        }
        __syncthreads();
    }

    #pragma unroll
    for (int i = 0; i < 8; i++) {
        float2 p0 = unpk(acc2[i][0]), p1 = unpk(acc2[i][1]);
        float2 p2 = unpk(acc2[i][2]), p3 = unpk(acc2[i][3]);
        size_t g = (size_t)(m0 + mt * 8 + i) * Hh + n0;
        *reinterpret_cast<float4*>(&out[g + nt * 4]) =
            make_float4(p0.x, p0.y, p1.x, p1.y);
        *reinterpret_cast<float4*>(&out[g + 64 + nt * 4]) =
            make_float4(p2.x, p2.y, p3.x, p3.y);
    }
}

// =========================================================================
// Kernel 2: recurrent scan, in place on d_out. Same topology as R1:
//   16 clusters x 8 CTAs; CTA rank r holds Wh cols [r*64, r*64+64) in smem
//   (k-major w_s[k][64]); cluster handles 8 batch rows; h exchanged through
//   d_out[t] + barrier.cluster.
//   Inner product now uses f32x2: acc lanes = (j, j+1); w pairs load
//   natively as 64-bit from w_s; h dup-packed on the alu pipe.
// =========================================================================
constexpr int W_S_ELEMS = Hh * 64;        // 32768 (w_s[k][64])
constexpr int H_S_PITCH = Hh + 4;         // 516
constexpr int H_S_ELEMS = 8 * H_S_PITCH;  // 4128
constexpr int RED_ELEMS = 8 * 512;        // 4096
constexpr int SCAN_SMEM_BYTES = (W_S_ELEMS + H_S_ELEMS + RED_ELEMS) * 4; // 163968

#define SCAN_ROW(hv, A0, A1)                                                  \
    {                                                                         \
        unsigned long long dx = dup2((hv).x);                                 \
        ffma2(A0, dx, w0.x); ffma2(A1, dx, w0.y);                             \
        unsigned long long dy = dup2((hv).y);                                 \
        ffma2(A0, dy, w1.x); ffma2(A1, dy, w1.y);                             \
        unsigned long long dz = dup2((hv).z);                                 \
        ffma2(A0, dz, w2.x); ffma2(A1, dz, w2.y);                             \
        unsigned long long dw = dup2((hv).w);                                 \
        ffma2(A0, dw, w3.x); ffma2(A1, dw, w3.y);                             \
    }

__global__ void __cluster_dims__(8, 1, 1) __launch_bounds__(256, 1)
rnn_scan_kernel(const float* __restrict__ Wh, float* __restrict__ out)
{
    extern __shared__ float smem[];
    float* w_s = smem;                       // [512][64]  (k-major)
    float* h_s = w_s + W_S_ELEMS;            // [8][516]
    float* red = h_s + H_S_ELEMS;            // [8][512]

    const int tid  = threadIdx.x;
    const int cid  = blockIdx.x >> 3;
    const int rank = blockIdx.x & 7;
    const int b0   = cid * 8;
    const int j0   = rank * 64;

    // one-time: Wh slice transposed into smem: w_s[k][jl] = Wh[j0+jl][k]
    for (int f = tid; f < 64 * 128; f += 256) {
        int jl = f >> 7;
        int k  = (f & 127) << 2;
        float4 v = *reinterpret_cast<const float4*>(&Wh[(size_t)(j0 + jl) * Hh + k]);
        w_s[(k + 0) * 64 + jl] = v.x;
        w_s[(k + 1) * 64 + jl] = v.y;
        w_s[(k + 2) * 64 + jl] = v.z;
        w_s[(k + 3) * 64 + jl] = v.w;
    }
    for (int i = tid; i < H_S_ELEMS; i += 256) h_s[i] = 0.0f;
    __syncthreads();

    const int kg = tid >> 5;            // 0..7  k range [kg*64, +64)
    const int bt = (tid >> 4) & 1;      // 0..1  b rows bt*4..+3
    const int jt = tid & 15;            // 0..15 j cols jt*4..+3 (2 f32x2 pairs)

    const int o0 = tid;
    const int o1 = tid + 256;
    const int b_l0 = o0 >> 6, j_l0 = o0 & 63;
    const int b_l1 = o1 >> 6, j_l1 = o1 & 63;

    const float* hp = h_s + (bt * 4) * H_S_PITCH + kg * 64;
    const float* wp = w_s + (kg * 64) * 64 + jt * 4;

    // prefetch xw for t=0
    float xw0 = out[((size_t)0 * Bb + b0) * Hh + j0 + b_l0 * Hh + j_l0];
    float xw1 = out[((size_t)0 * Bb + b0) * Hh + j0 + b_l1 * Hh + j_l1];

    for (int t = 0; t < Tt; t++) {
        // ---- partial dot products with f32x2 (acc lanes = j pair)
        unsigned long long A00 = 0, A01 = 0, A10 = 0, A11 = 0;
        unsigned long long A20 = 0, A21 = 0, A30 = 0, A31 = 0;

        #pragma unroll 4
        for (int kq = 0; kq < 64; kq += 4) {
            ulonglong2 w0 = *reinterpret_cast<const ulonglong2*>(wp + (kq + 0) * 64);
            ulonglong2 w1 = *reinterpret_cast<const ulonglong2*>(wp + (kq + 1) * 64);
            ulonglong2 w2 = *reinterpret_cast<const ulonglong2*>(wp + (kq + 2) * 64);
            ulonglong2 w3 = *reinterpret_cast<const ulonglong2*>(wp + (kq + 3) * 64);
            float4 h0v = *reinterpret_cast<const float4*>(hp + 0 * H_S_PITCH + kq);
            float4 h1v = *reinterpret_cast<const float4*>(hp + 1 * H_S_PITCH + kq);
            float4 h2v = *reinterpret_cast<const float4*>(hp + 2 * H_S_PITCH + kq);
            float4 h3v = *reinterpret_cast<const float4*>(hp + 3 * H_S_PITCH + kq);
            SCAN_ROW(h0v, A00, A01);
            SCAN_ROW(h1v, A10, A11);
            SCAN_ROW(h2v, A20, A21);
            SCAN_ROW(h3v, A30, A31);
        }

        // ---- cross-kg reduction via smem
        {
            float* rp = red + kg * 512 + (bt * 4) * 64 + jt * 4;
            float2 p0, p1;
            p0 = unpk(A00); p1 = unpk(A01);
            *reinterpret_cast<float4*>(rp + 0 * 64) = make_float4(p0.x, p0.y, p1.x, p1.y);
            p0 = unpk(A10); p1 = unpk(A11);
            *reinterpret_cast<float4*>(rp + 1 * 64) = make_float4(p0.x, p0.y, p1.x, p1.y);
            p0 = unpk(A20); p1 = unpk(A21);
            *reinterpret_cast<float4*>(rp + 2 * 64) = make_float4(p0.x, p0.y, p1.x, p1.y);
            p0 = unpk(A30); p1 = unpk(A31);
            *reinterpret_cast<float4*>(rp + 3 * 64) = make_float4(p0.x, p0.y, p1.x, p1.y);
        }
        __syncthreads();

        float s0 = 0.0f, s1 = 0.0f;
        #pragma unroll
        for (int g = 0; g < 8; g++) {
            s0 += red[g * 512 + o0];
            s1 += red[g * 512 + o1];
        }

        float h0 = tanh_acc(xw0 + s0);
        float h1 = tanh_acc(xw1 + s1);

        // write h_t over xw in d_out[t]
        float* ob = out + ((size_t)t * Bb + b0) * Hh + j0;
        ob[b_l0 * Hh + j_l0] = h0;
        ob[b_l1 * Hh + j_l1] = h1;
        if (t == Tt - 1) {
            float* tb = out + TBH + (size_t)b0 * Hh + j0;
            tb[b_l0 * Hh + j_l0] = h0;
            tb[b_l1 * Hh + j_l1] = h1;
        }

        // prefetch next step's xw BEFORE arrive (ordered by the release)
        {
            int tn = (t + 1 < Tt) ? (t + 1) : (Tt - 1);
            const float* xwb = out + ((size_t)tn * Bb + b0) * Hh + j0;
            xw0 = xwb[b_l0 * Hh + j_l0];
            xw1 = xwb[b_l1 * Hh + j_l1];
        }

        // ---- cluster barrier: release our h slice, acquire peers' slices
        asm volatile("barrier.cluster.arrive.aligned;" ::: "memory");
        asm volatile("barrier.cluster.wait.aligned;"   ::: "memory");

        // ---- reload full h_t for our 8 batch rows into h_s
        const float* hg = out + ((size_t)t * Bb + b0) * Hh;
        #pragma unroll
        for (int r = 0; r < 4; r++) {
            int f = tid + r * 256;
            int b = f >> 7;
            int k = (f & 127) << 2;
            float4 v = *reinterpret_cast<const float4*>(hg + (size_t)b * Hh + k);
            *reinterpret_cast<float4*>(h_s + b * H_S_PITCH + k) = v;
        }
        __syncthreads();
    }
}

// =========================================================================
// launcher
// =========================================================================
extern "C" void kernel_launch(void* const* d_in, const int* in_sizes, int n_in,
                              void* d_out, int out_size)
{
    const float* x  = (const float*)d_in[0];   // [T, B, I]
    const float* Wi = (const float*)d_in[1];   // [H, I]
    const float* Wh = (const float*)d_in[2];   // [H, H]
    float* out = (float*)d_out;

    (void)in_sizes; (void)n_in; (void)out_size;

    xw_gemm_kernel<<<(Tt * Bb / 128) * (Hh / 128), 256>>>(x, Wi, out);

    cudaFuncSetAttribute(rnn_scan_kernel,
                         cudaFuncAttributeMaxDynamicSharedMemorySize,
                         SCAN_SMEM_BYTES);
    rnn_scan_kernel<<<128, 256, SCAN_SMEM_BYTES>>>(Wh, out);
}

// round 3
// speedup vs baseline: 1.1160x; 1.1160x over previous
#include <cuda_runtime.h>
#include <cstdint>

// Problem constants
constexpr int Tt = 1024;   // timesteps
constexpr int Bb = 128;    // batch
constexpr int Ii = 256;    // input dim
constexpr int Hh = 512;    // hidden dim
constexpr long long TBH = (long long)Tt * Bb * Hh;   // output region size

using ull = unsigned long long;

// -------------------------------------------------------------------------
// packed fp32 helpers (Blackwell f32x2 pipe; exact fp32 semantics)
// -------------------------------------------------------------------------
__device__ __forceinline__ void ffma2(ull& d, ull a, ull b) {
    asm("fma.rn.f32x2 %0, %1, %2, %0;" : "+l"(d) : "l"(a), "l"(b));
}
__device__ __forceinline__ ull dup2(float x) {
    ull r;
    asm("mov.b64 %0, {%1, %1};" : "=l"(r) : "f"(x));
    return r;
}
__device__ __forceinline__ float2 unpk(ull v) {
    float2 r;
    asm("mov.b64 {%0, %1}, %2;" : "=f"(r.x), "=f"(r.y) : "l"(v));
    return r;
}

// accurate tanh that survives --use_fast_math
__device__ __forceinline__ float tanh_acc(float x) {
    float ax = fabsf(x);
    float e  = __expf(-2.0f * ax);
    float r  = (1.0f - e) / (1.0f + e);
    return copysignf(r, x);
}

// =========================================================================
// Kernel 1: xw = x @ Wi^T  into d_out[0 : T*B*H)   (unchanged from R2)
// =========================================================================
__global__ void __launch_bounds__(256, 2)
xw_gemm_kernel(const float* __restrict__ x,
               const float* __restrict__ Wi,
               float* __restrict__ out)
{
    __shared__ float As[32][132];   // [k][m], padded
    __shared__ float Bs[32][132];   // [k][n], padded

    const int m0 = (blockIdx.x >> 2) * 128;
    const int n0 = (blockIdx.x & 3) * 128;
    const int tid = threadIdx.x;
    const int mt = tid >> 4;                  // 0..15 -> m rows mt*8..+7
    const int nt = tid & 15;                  // 0..15 -> n cols 4nt..+3, 64+4nt..+3

    ull acc2[8][4];
    #pragma unroll
    for (int i = 0; i < 8; i++)
        #pragma unroll
        for (int j = 0; j < 4; j++) acc2[i][j] = 0ULL;

    for (int k0 = 0; k0 < Ii; k0 += 32) {
        #pragma unroll
        for (int r = 0; r < 4; r++) {
            int f   = tid + r * 256;
            int row = f >> 3;
            int kq  = (f & 7) << 2;
            float4 va = *reinterpret_cast<const float4*>(
                &x[(size_t)(m0 + row) * Ii + k0 + kq]);
            As[kq + 0][row] = va.x; As[kq + 1][row] = va.y;
            As[kq + 2][row] = va.z; As[kq + 3][row] = va.w;
            float4 vb = *reinterpret_cast<const float4*>(
                &Wi[(size_t)(n0 + row) * Ii + k0 + kq]);
            Bs[kq + 0][row] = vb.x; Bs[kq + 1][row] = vb.y;
            Bs[kq + 2][row] = vb.z; Bs[kq + 3][row] = vb.w;
        }
        __syncthreads();

        #pragma unroll 4
        for (int kk = 0; kk < 32; kk++) {
            float4 av0 = *reinterpret_cast<const float4*>(&As[kk][mt * 8]);
            float4 av1 = *reinterpret_cast<const float4*>(&As[kk][mt * 8 + 4]);
            ulonglong2 b0 = *reinterpret_cast<const ulonglong2*>(&Bs[kk][nt * 4]);
            ulonglong2 b1 = *reinterpret_cast<const ulonglong2*>(&Bs[kk][64 + nt * 4]);
            float am[8] = {av0.x, av0.y, av0.z, av0.w, av1.x, av1.y, av1.z, av1.w};
            #pragma unroll
            for (int i = 0; i < 8; i++) {
                ull d = dup2(am[i]);
                ffma2(acc2[i][0], d, b0.x);
                ffma2(acc2[i][1], d, b0.y);
                ffma2(acc2[i][2], d, b1.x);
                ffma2(acc2[i][3], d, b1.y);
            }
        }
        __syncthreads();
    }

    #pragma unroll
    for (int i = 0; i < 8; i++) {
        float2 p0 = unpk(acc2[i][0]), p1 = unpk(acc2[i][1]);
        float2 p2 = unpk(acc2[i][2]), p3 = unpk(acc2[i][3]);
        size_t g = (size_t)(m0 + mt * 8 + i) * Hh + n0;
        *reinterpret_cast<float4*>(&out[g + nt * 4]) =
            make_float4(p0.x, p0.y, p1.x, p1.y);
        *reinterpret_cast<float4*>(&out[g + 64 + nt * 4]) =
            make_float4(p2.x, p2.y, p3.x, p3.y);
    }
}

// =========================================================================
// Kernel 2: recurrent scan, Wh RESIDENT IN REGISTERS.
//   16 clusters x 8 CTAs; cluster c owns batch rows [c*8, c*8+8);
//   CTA rank r owns output columns [r*64, r*64+64).
//   Thread (kg = warp id 0..7, jg = lane 0..31) owns:
//     Wh[j0+jg][kg*64 .. +64)  and  Wh[j0+jg+32][kg*64 .. +64)
//   as 64 f32x2 register pairs packed over k. Accumulators are f32x2 with
//   lanes = (k even / k odd) partial sums; one horizontal add at the end.
//   h loads are warp-wide broadcast LDS.128 (all lanes same address).
//   Cross-kg (cross-warp) reduction via smem; h exchanged through
//   d_out[t] + barrier.cluster as before.
// =========================================================================
constexpr int H_S_PITCH = Hh + 4;         // 516 floats (16B-aligned rows)
constexpr int H_S_ELEMS = 8 * H_S_PITCH;  // 4128
constexpr int RED_ELEMS = 8 * 8 * 64;     // red[kg][b][j] = 4096

__global__ void __cluster_dims__(8, 1, 1) __launch_bounds__(256, 1)
rnn_scan_kernel(const float* __restrict__ Wh, float* __restrict__ out)
{
    __shared__ float h_s[H_S_ELEMS];
    __shared__ float red[RED_ELEMS];

    const int tid  = threadIdx.x;
    const int cid  = blockIdx.x >> 3;
    const int rank = blockIdx.x & 7;
    const int b0   = cid * 8;                // batch rows of this cluster
    const int j0   = rank * 64;              // output columns of this CTA

    const int kg = tid >> 5;                 // warp id: k range [kg*64, +64)
    const int jg = tid & 31;                 // lane: j cols j0+jg, j0+jg+32
    const int kbase = kg * 64;

    // ---- one-time: load this thread's 128 Wh weights into registers,
    //      packed over k: w?a/w?b[kp] = (Wh[j][kbase+2kp], Wh[j][kbase+2kp+1])
    ull w2a[32], w2b[32];
    {
        const ull* wr0 = reinterpret_cast<const ull*>(
            Wh + (size_t)(j0 + jg) * Hh + kbase);
        const ull* wr1 = reinterpret_cast<const ull*>(
            Wh + (size_t)(j0 + jg + 32) * Hh + kbase);
        #pragma unroll
        for (int kp = 0; kp < 32; kp++) {
            w2a[kp] = wr0[kp];
            w2b[kp] = wr1[kp];
        }
    }

    // ---- h_{-1} = 0
    for (int i = tid; i < H_S_ELEMS; i += 256) h_s[i] = 0.0f;
    __syncthreads();

    // epilogue output assignment (2 outputs per thread): o = b_l*64 + j_l
    const int o0 = tid;
    const int o1 = tid + 256;
    const int b_l0 = o0 >> 6, j_l0 = o0 & 63;
    const int b_l1 = o1 >> 6, j_l1 = o1 & 63;

    // prefetch xw for t=0
    float xw0 = out[((size_t)0 * Bb + b0) * Hh + j0 + b_l0 * Hh + j_l0];
    float xw1 = out[((size_t)0 * Bb + b0) * Hh + j0 + b_l1 * Hh + j_l1];

    for (int t = 0; t < Tt; t++) {
        // ---- partial dot products, f32x2 packed over k
        ull acc[8][2];
        #pragma unroll
        for (int b = 0; b < 8; b++) { acc[b][0] = 0ULL; acc[b][1] = 0ULL; }

        #pragma unroll
        for (int q = 0; q < 16; q++) {
            #pragma unroll
            for (int b = 0; b < 8; b++) {
                // broadcast load: all 32 lanes read the same 16 bytes
                ulonglong2 hv = *reinterpret_cast<const ulonglong2*>(
                    h_s + b * H_S_PITCH + kbase + q * 4);
                ffma2(acc[b][0], hv.x, w2a[2 * q]);
                ffma2(acc[b][1], hv.x, w2b[2 * q]);
                ffma2(acc[b][0], hv.y, w2a[2 * q + 1]);
                ffma2(acc[b][1], hv.y, w2b[2 * q + 1]);
            }
        }

        // ---- horizontal add + cross-warp (kg) reduction via smem
        #pragma unroll
        for (int b = 0; b < 8; b++) {
            float2 p0 = unpk(acc[b][0]);
            float2 p1 = unpk(acc[b][1]);
            red[kg * 512 + b * 64 + jg]      = p0.x + p0.y;
            red[kg * 512 + b * 64 + jg + 32] = p1.x + p1.y;
        }
        __syncthreads();

        float s0 = 0.0f, s1 = 0.0f;
        #pragma unroll
        for (int g = 0; g < 8; g++) {
            s0 += red[g * 512 + o0];
            s1 += red[g * 512 + o1];
        }

        float h0 = tanh_acc(xw0 + s0);
        float h1 = tanh_acc(xw1 + s1);

        // write h_t over xw in d_out[t]
        float* ob = out + ((size_t)t * Bb + b0) * Hh + j0;
        ob[b_l0 * Hh + j_l0] = h0;
        ob[b_l1 * Hh + j_l1] = h1;
        if (t == Tt - 1) {   // h_final tail
            float* tb = out + TBH + (size_t)b0 * Hh + j0;
            tb[b_l0 * Hh + j_l0] = h0;
            tb[b_l1 * Hh + j_l1] = h1;
        }

        // prefetch next step's xw (same thread overwrites it next step)
        {
            int tn = (t + 1 < Tt) ? (t + 1) : (Tt - 1);
            const float* xwb = out + ((size_t)tn * Bb + b0) * Hh + j0;
            xw0 = xwb[b_l0 * Hh + j_l0];
            xw1 = xwb[b_l1 * Hh + j_l1];
        }

        // ---- cluster barrier: release our h slice, acquire peers' slices
        asm volatile("barrier.cluster.arrive.aligned;" ::: "memory");
        asm volatile("barrier.cluster.wait.aligned;"   ::: "memory");

        // ---- reload full h_t for our 8 batch rows (16 KB from L2)
        const float* hg = out + ((size_t)t * Bb + b0) * Hh;
        #pragma unroll
        for (int r = 0; r < 4; r++) {
            int f = tid + r * 256;           // float4 index 0..1023
            int b = f >> 7;
            int k = (f & 127) << 2;
            float4 v = *reinterpret_cast<const float4*>(hg + (size_t)b * Hh + k);
            *reinterpret_cast<float4*>(h_s + b * H_S_PITCH + k) = v;
        }
        __syncthreads();
    }
}

// =========================================================================
// launcher
// =========================================================================
extern "C" void kernel_launch(void* const* d_in, const int* in_sizes, int n_in,
                              void* d_out, int out_size)
{
    const float* x  = (const float*)d_in[0];   // [T, B, I]
    const float* Wi = (const float*)d_in[1];   // [H, I]
    const float* Wh = (const float*)d_in[2];   // [H, H]
    float* out = (float*)d_out;

    (void)in_sizes; (void)n_in; (void)out_size;

    xw_gemm_kernel<<<(Tt * Bb / 128) * (Hh / 128), 256>>>(x, Wi, out);

    rnn_scan_kernel<<<128, 256>>>(Wh, out);
}